// round 2
// baseline (speedup 1.0000x reference)
#include <cuda_runtime.h>
#include <math.h>

#define Bb 4
#define Tt 2048
#define Dd 256
#define BT (Bb*Tt)
#define BTD (Bb*Tt*Dd)

// Scratch (static __device__ — no allocations allowed)
__device__ float g_q[BTD];
__device__ float g_k[BTD];   // scaled by 1/sqrt(D)
__device__ float g_v[BTD];
__device__ float g_li[BTD];  // log_i, overwritten in place with i_s by chan_scan
__device__ float g_lf[BTD];  // log_f, overwritten in place with f_s by chan_scan
__device__ float g_o[BTD];   // o_pre
__device__ float g_n[BTD];
__device__ float g_den[BT];

// ---------------------------------------------------------------------------
// Kernel 1: fused projection GEMM  (8192 x 1536 x 256, fp32)
// N segments: [0,256)=q  [256,512)=k  [512,768)=v  [768,1536)=gates(Wg)
// ---------------------------------------------------------------------------
__global__ __launch_bounds__(256) void proj_gemm(
    const float* __restrict__ x,
    const float* __restrict__ Wq, const float* __restrict__ bq,
    const float* __restrict__ Wk, const float* __restrict__ bk,
    const float* __restrict__ Wv, const float* __restrict__ bv,
    const float* __restrict__ Wg, const float* __restrict__ bg,
    const float* __restrict__ ib)
{
    __shared__ float As[64][20];   // [m][k] padded
    __shared__ float Bs[16][64];   // [k][n]

    const int tid   = threadIdx.x;
    const int mBase = blockIdx.y * 64;
    const int nBase = blockIdx.x * 64;

    const float* W;  const float* bias;  float* outArr;
    int ldw, colW, outCol, mode;
    if (nBase < 256)      { W = Wq; ldw = 256; colW = nBase;       bias = bq; outArr = g_q;  mode = 0; }
    else if (nBase < 512) { W = Wk; ldw = 256; colW = nBase - 256; bias = bk; outArr = g_k;  mode = 1; }
    else if (nBase < 768) { W = Wv; ldw = 256; colW = nBase - 512; bias = bv; outArr = g_v;  mode = 0; }
    else {
        W = Wg; ldw = 768; colW = nBase - 768; bias = bg;
        int gi = colW >> 8;
        outArr = (gi == 0) ? g_li : ((gi == 1) ? g_lf : g_o);
        mode   = (gi == 0) ? 2 : ((gi == 1) ? 3 : 0);
    }
    outCol = (nBase < 768) ? colW : (colW & 255);

    const int aRow = tid >> 2, aK = (tid & 3) << 2;
    const int bK   = tid >> 4, bN = (tid & 15) << 2;
    const int tx   = tid & 15, ty = tid >> 4;

    float acc[4][4] = {};

    for (int k0 = 0; k0 < 256; k0 += 16) {
        float4 av  = *(const float4*)(x + (size_t)(mBase + aRow) * 256 + k0 + aK);
        float4 bv4 = *(const float4*)(W + (size_t)(k0 + bK) * ldw + colW + bN);
        __syncthreads();
        *(float4*)&As[aRow][aK] = av;
        *(float4*)&Bs[bK][bN]   = bv4;
        __syncthreads();
        #pragma unroll
        for (int kk = 0; kk < 16; kk++) {
            float a0 = As[ty*4+0][kk];
            float a1 = As[ty*4+1][kk];
            float a2 = As[ty*4+2][kk];
            float a3 = As[ty*4+3][kk];
            float4 bb = *(const float4*)&Bs[kk][tx*4];
            acc[0][0] = fmaf(a0, bb.x, acc[0][0]); acc[0][1] = fmaf(a0, bb.y, acc[0][1]);
            acc[0][2] = fmaf(a0, bb.z, acc[0][2]); acc[0][3] = fmaf(a0, bb.w, acc[0][3]);
            acc[1][0] = fmaf(a1, bb.x, acc[1][0]); acc[1][1] = fmaf(a1, bb.y, acc[1][1]);
            acc[1][2] = fmaf(a1, bb.z, acc[1][2]); acc[1][3] = fmaf(a1, bb.w, acc[1][3]);
            acc[2][0] = fmaf(a2, bb.x, acc[2][0]); acc[2][1] = fmaf(a2, bb.y, acc[2][1]);
            acc[2][2] = fmaf(a2, bb.z, acc[2][2]); acc[2][3] = fmaf(a2, bb.w, acc[2][3]);
            acc[3][0] = fmaf(a3, bb.x, acc[3][0]); acc[3][1] = fmaf(a3, bb.y, acc[3][1]);
            acc[3][2] = fmaf(a3, bb.z, acc[3][2]); acc[3][3] = fmaf(a3, bb.w, acc[3][3]);
        }
    }

    #pragma unroll
    for (int i = 0; i < 4; i++) {
        int row = mBase + ty*4 + i;
        #pragma unroll
        for (int j = 0; j < 4; j++) {
            int nl = tx*4 + j;
            float val = acc[i][j] + bias[colW + nl];
            if (mode == 1) {
                val *= 0.0625f;                              // 1/sqrt(256)
            } else if (mode == 2) {
                val += ib[outCol + nl];
                val = 10.0f * tanhf(val * 0.1f);             // softcap
            } else if (mode == 3) {
                val = -(fmaxf(val, 0.0f) + log1pf(__expf(-fabsf(val))));  // -softplus
            }
            outArr[(size_t)row * 256 + outCol + nl] = val;
        }
    }
}

// ---------------------------------------------------------------------------
// Kernel 2: per-channel scan  (m, i_s, f_s, n)   one thread per (b,d)
// ---------------------------------------------------------------------------
__device__ __forceinline__ void cs_load(size_t base, int g,
    float (&li)[8], float (&lf)[8], float (&kk)[8])
{
    #pragma unroll
    for (int u = 0; u < 8; u++) {
        size_t idx = base + (size_t)(g*8 + u) * Dd;
        li[u] = g_li[idx]; lf[u] = g_lf[idx]; kk[u] = g_k[idx];
    }
}
__device__ __forceinline__ void cs_proc(size_t base, int g,
    const float (&li)[8], const float (&lf)[8], const float (&kk)[8],
    float& m, float& n)
{
    #pragma unroll
    for (int u = 0; u < 8; u++) {
        size_t idx = base + (size_t)(g*8 + u) * Dd;
        float mn = fmaxf(lf[u] + m, li[u]);
        float is = __expf(li[u] - mn);
        float fs = __expf(lf[u] + m - mn);
        n = fmaf(fs, n, is * kk[u]);
        g_li[idx] = is;
        g_lf[idx] = fs;
        g_n[idx]  = n;
        m = mn;
    }
}
__global__ __launch_bounds__(32) void chan_scan()
{
    const int b = blockIdx.x >> 3;
    const int d = ((blockIdx.x & 7) << 5) + threadIdx.x;
    size_t base = (size_t)b * Tt * Dd + d;
    float m = 0.0f, n = 0.0f;
    float liA[8], lfA[8], kA[8], liB[8], lfB[8], kB[8];
    const int NG = Tt / 8;   // 256
    cs_load(base, 0, liA, lfA, kA);
    for (int g = 0; g < NG; g += 2) {
        cs_load(base, g + 1, liB, lfB, kB);
        cs_proc(base, g, liA, lfA, kA, m, n);
        if (g + 2 < NG) cs_load(base, g + 2, liA, lfA, kA);
        cs_proc(base, g + 1, liB, lfB, kB, m, n);
    }
}

// ---------------------------------------------------------------------------
// Kernel 3: denom[b,t] = max(|n_t . q_t|, 1e-6)    one warp per (b,t)
// ---------------------------------------------------------------------------
__global__ __launch_bounds__(256) void denom_kernel()
{
    const int gw   = blockIdx.x * 8 + (threadIdx.x >> 5);
    const int lane = threadIdx.x & 31;
    size_t base = (size_t)gw * Dd + lane * 8;
    float4 n1 = *(const float4*)&g_n[base];
    float4 n2 = *(const float4*)&g_n[base + 4];
    float4 q1 = *(const float4*)&g_q[base];
    float4 q2 = *(const float4*)&g_q[base + 4];
    float s = n1.x*q1.x + n1.y*q1.y + n1.z*q1.z + n1.w*q1.w
            + n2.x*q2.x + n2.y*q2.y + n2.z*q2.z + n2.w*q2.w;
    #pragma unroll
    for (int o = 16; o; o >>= 1) s += __shfl_xor_sync(0xffffffffu, s, o);
    if (lane == 0) g_den[gw] = fmaxf(fabsf(s), 1e-6f);
}

// ---------------------------------------------------------------------------
// Kernel 4: main sequential scan.  CTA = 8 warps = 8 M-rows of one batch.
// Warp w owns M[row,:] in registers (8 floats/lane). cp.async 4-stage pipeline.
// ---------------------------------------------------------------------------
#define STAGES 4
__device__ __forceinline__ void cpa16(void* sm, const void* g) {
    unsigned s = (unsigned)__cvta_generic_to_shared(sm);
    asm volatile("cp.async.ca.shared.global [%0], [%1], 16;" :: "r"(s), "l"(g));
}
__device__ __forceinline__ void cpa4(void* sm, const void* g) {
    unsigned s = (unsigned)__cvta_generic_to_shared(sm);
    asm volatile("cp.async.ca.shared.global [%0], [%1], 4;" :: "r"(s), "l"(g));
}

__global__ __launch_bounds__(256) void main_scan(float* __restrict__ out)
{
    __shared__ __align__(16) float s_kq[STAGES][512];  // k[256] | q[256]
    __shared__ __align__(16) float s_sc[STAGES][32];   // v[8] is[8] fs[8] op[8]
    __shared__ __align__(16) float s_den[STAGES][4];

    const int tid     = threadIdx.x;
    const int w       = tid >> 5;
    const int lane    = tid & 31;
    const int b       = blockIdx.x >> 5;
    const int rowBase = (blockIdx.x & 31) << 3;
    const size_t bBase = (size_t)b * Tt * Dd;

    auto issue = [&](int st, int t) {
        size_t base = bBase + (size_t)t * Dd;
        if (tid < 64) {
            cpa16(&s_kq[st][tid * 4], g_k + base + tid * 4);
        } else if (tid < 128) {
            cpa16(&s_kq[st][256 + (tid - 64) * 4], g_q + base + (tid - 64) * 4);
        } else if (tid < 136) {
            int a = (tid - 128) >> 1, p = (tid - 128) & 1;
            const float* sp = (a == 0) ? g_v : (a == 1) ? g_li : (a == 2) ? g_lf : g_o;
            cpa16(&s_sc[st][a * 8 + p * 4], sp + base + rowBase + p * 4);
        } else if (tid == 136) {
            cpa4(&s_den[st][0], &g_den[(size_t)b * Tt + t]);
        }
    };

    float Mr[8];
    #pragma unroll
    for (int i = 0; i < 8; i++) Mr[i] = 0.0f;

    #pragma unroll
    for (int s = 0; s < STAGES - 1; ++s) {
        issue(s, s);
        asm volatile("cp.async.commit_group;");
    }

    for (int t = 0; t < Tt; ++t) {
        asm volatile("cp.async.wait_group %0;" :: "n"(STAGES - 2));
        __syncthreads();
        int tp = t + STAGES - 1;
        if (tp < Tt) issue(tp & (STAGES - 1), tp);
        asm volatile("cp.async.commit_group;");

        const int st = t & (STAGES - 1);
        const float4 ka = *(const float4*)&s_kq[st][lane * 8];
        const float4 kb = *(const float4*)&s_kq[st][lane * 8 + 4];
        const float4 qa = *(const float4*)&s_kq[st][256 + lane * 8];
        const float4 qb = *(const float4*)&s_kq[st][256 + lane * 8 + 4];
        const float vv  = s_sc[st][w];
        const float is  = s_sc[st][8 + w];
        const float fs  = s_sc[st][16 + w];
        const float op  = s_sc[st][24 + w];
        const float den = s_den[st][0];
        const float iv  = is * vv;

        Mr[0] = fmaf(fs, Mr[0], iv * ka.x);
        Mr[1] = fmaf(fs, Mr[1], iv * ka.y);
        Mr[2] = fmaf(fs, Mr[2], iv * ka.z);
        Mr[3] = fmaf(fs, Mr[3], iv * ka.w);
        Mr[4] = fmaf(fs, Mr[4], iv * kb.x);
        Mr[5] = fmaf(fs, Mr[5], iv * kb.y);
        Mr[6] = fmaf(fs, Mr[6], iv * kb.z);
        Mr[7] = fmaf(fs, Mr[7], iv * kb.w);

        float a0 = Mr[0] * qa.x;
        float a1 = Mr[1] * qa.y;
        a0 = fmaf(Mr[2], qa.z, a0);
        a1 = fmaf(Mr[3], qa.w, a1);
        a0 = fmaf(Mr[4], qb.x, a0);
        a1 = fmaf(Mr[5], qb.y, a1);
        a0 = fmaf(Mr[6], qb.z, a0);
        a1 = fmaf(Mr[7], qb.w, a1);
        float acc = a0 + a1;

        #pragma unroll
        for (int o = 16; o; o >>= 1) acc += __shfl_xor_sync(0xffffffffu, acc, o);

        if (lane == 0) {
            float sig = 1.0f / (1.0f + __expf(-op));
            out[bBase + (size_t)t * Dd + rowBase + w] = sig * acc / den;
        }
    }
}

// ---------------------------------------------------------------------------
// Kernel 5: RMSNorm in place on d_out.  One warp per (b,t) row.
// ---------------------------------------------------------------------------
__global__ __launch_bounds__(256) void rmsnorm_kernel(float* __restrict__ out,
                                                      const float* __restrict__ ns)
{
    const int gw   = blockIdx.x * 8 + (threadIdx.x >> 5);
    const int lane = threadIdx.x & 31;
    size_t base = (size_t)gw * Dd + lane * 8;
    float4 a = *(const float4*)&out[base];
    float4 c = *(const float4*)&out[base + 4];
    float ss = a.x*a.x + a.y*a.y + a.z*a.z + a.w*a.w
             + c.x*c.x + c.y*c.y + c.z*c.z + c.w*c.w;
    #pragma unroll
    for (int o = 16; o; o >>= 1) ss += __shfl_xor_sync(0xffffffffu, ss, o);
    float rinv = rsqrtf(ss * (1.0f / Dd) + 1e-8f);
    float4 s1 = *(const float4*)&ns[lane * 8];
    float4 s2 = *(const float4*)&ns[lane * 8 + 4];
    a.x *= rinv * s1.x; a.y *= rinv * s1.y; a.z *= rinv * s1.z; a.w *= rinv * s1.w;
    c.x *= rinv * s2.x; c.y *= rinv * s2.y; c.z *= rinv * s2.z; c.w *= rinv * s2.w;
    *(float4*)&out[base]     = a;
    *(float4*)&out[base + 4] = c;
}

// ---------------------------------------------------------------------------
extern "C" void kernel_launch(void* const* d_in, const int* in_sizes, int n_in,
                              void* d_out, int out_size)
{
    const float* x  = (const float*)d_in[0];
    const float* Wq = (const float*)d_in[1];
    const float* bq = (const float*)d_in[2];
    const float* Wk = (const float*)d_in[3];
    const float* bk = (const float*)d_in[4];
    const float* Wv = (const float*)d_in[5];
    const float* bv = (const float*)d_in[6];
    const float* Wg = (const float*)d_in[7];
    const float* bg = (const float*)d_in[8];
    const float* ib = (const float*)d_in[9];
    const float* ns = (const float*)d_in[10];
    float* out = (float*)d_out;

    dim3 ggrid(24, 128);   // N tiles x M tiles
    proj_gemm<<<ggrid, 256>>>(x, Wq, bq, Wk, bk, Wv, bv, Wg, bg, ib);
    chan_scan<<<32, 32>>>();
    denom_kernel<<<1024, 256>>>();
    main_scan<<<128, 256>>>(out);
    rmsnorm_kernel<<<1024, 256>>>(out, ns);
}